// round 1
// baseline (speedup 1.0000x reference)
#include <cuda_runtime.h>
#include <cstdint>

// Problem shape (fixed)
#define Bz 4
#define Sz 2048
#define Dz 1024
#define Hz 16
#define DHz 64
// derived
#define HD (Hz*DHz)          // 1024
#define QKV_N (3*HD)         // 3072
#define Mrows (Bz*Sz)        // 8192

// Scratch (device globals: allocation-free per harness rules)
__device__ float g_qkv[(size_t)Mrows * QKV_N];   // [b,s,t,h,e]  96 MB
__device__ float g_attn[(size_t)Mrows * HD];     // [b,s,h,e]    32 MB

// ---------------------------------------------------------------------------
// Tiled SGEMM + bias: C[M,N] = A[M,K] @ B[K,N] + bias[N]
// A,B,C row-major. M%128==0, N%128==0, K%8==0 guaranteed by shapes.
// ---------------------------------------------------------------------------
__global__ __launch_bounds__(256)
void sgemm_bias(int M, int N, int K,
                const float* __restrict__ A,
                const float* __restrict__ Bm,
                const float* __restrict__ bias,
                float* __restrict__ C)
{
    constexpr int BM = 128, BN = 128, BK = 8, TM = 8, TN = 8;
    __shared__ float As[BK][BM];
    __shared__ float Bs[BK][BN];

    const int cRow = blockIdx.y;
    const int cCol = blockIdx.x;
    const int tid  = threadIdx.x;

    const int threadCol = tid % (BN / TN);  // 0..15
    const int threadRow = tid / (BN / TN);  // 0..15

    A  += (size_t)cRow * BM * K;
    Bm += (size_t)cCol * BN;
    C  += (size_t)cRow * BM * N + (size_t)cCol * BN;
    const float* biasp = bias + (size_t)cCol * BN;

    const int innerRowA = tid / (BK / 4);   // /2 -> 0..127
    const int innerColA = tid % (BK / 4);   // 0..1
    const int innerRowB = tid / (BN / 4);   // /32 -> 0..7
    const int innerColB = tid % (BN / 4);   // 0..31

    float acc[TM][TN];
#pragma unroll
    for (int i = 0; i < TM; i++)
#pragma unroll
        for (int j = 0; j < TN; j++) acc[i][j] = 0.0f;

    float regM[TM], regN[TN];

    for (int k0 = 0; k0 < K; k0 += BK) {
        // load A tile (transposed into As)
        float4 av = *(const float4*)(A + (size_t)innerRowA * K + innerColA * 4);
        As[innerColA * 4 + 0][innerRowA] = av.x;
        As[innerColA * 4 + 1][innerRowA] = av.y;
        As[innerColA * 4 + 2][innerRowA] = av.z;
        As[innerColA * 4 + 3][innerRowA] = av.w;
        // load B tile
        *(float4*)&Bs[innerRowB][innerColB * 4] =
            *(const float4*)(Bm + (size_t)innerRowB * N + innerColB * 4);
        __syncthreads();

        A  += BK;
        Bm += (size_t)BK * N;

#pragma unroll
        for (int k = 0; k < BK; k++) {
#pragma unroll
            for (int i = 0; i < TM; i++) regM[i] = As[k][threadRow * TM + i];
#pragma unroll
            for (int j = 0; j < TN; j++) regN[j] = Bs[k][threadCol * TN + j];
#pragma unroll
            for (int i = 0; i < TM; i++)
#pragma unroll
                for (int j = 0; j < TN; j++)
                    acc[i][j] += regM[i] * regN[j];
        }
        __syncthreads();
    }

    // epilogue: bias add + vectorized store
#pragma unroll
    for (int i = 0; i < TM; i++) {
        const int row = threadRow * TM + i;
#pragma unroll
        for (int j4 = 0; j4 < TN / 4; j4++) {
            const int col = threadCol * TN + j4 * 4;
            float4 bv = *(const float4*)(biasp + col);
            float4 cv;
            cv.x = acc[i][j4 * 4 + 0] + bv.x;
            cv.y = acc[i][j4 * 4 + 1] + bv.y;
            cv.z = acc[i][j4 * 4 + 2] + bv.z;
            cv.w = acc[i][j4 * 4 + 3] + bv.w;
            *(float4*)(C + (size_t)row * N + col) = cv;
        }
    }
}

// ---------------------------------------------------------------------------
// Causal flash attention (fp32). One thread = one query row.
// Block = 128 query rows for one (b,h). K/V tiles of 32x64 in smem.
// ---------------------------------------------------------------------------
__global__ __launch_bounds__(128)
void attn_kernel()
{
    constexpr int KT = 32;           // keys per tile
    const int bh = blockIdx.x;       // 0..B*H-1
    const int b  = bh / Hz;
    const int h  = bh % Hz;
    const int qt = blockIdx.y;       // 0..S/128-1
    const int qi = qt * 128 + threadIdx.x;   // global query row within sequence

    const float* __restrict__ qkv = g_qkv;
    const size_t qbase = ((size_t)(b * Sz + qi) * 3) * HD + h * DHz;   // t=0 (Q)

    float q[DHz];
#pragma unroll
    for (int e4 = 0; e4 < DHz / 4; e4++) {
        float4 t = *(const float4*)(qkv + qbase + e4 * 4);
        q[4 * e4 + 0] = t.x; q[4 * e4 + 1] = t.y;
        q[4 * e4 + 2] = t.z; q[4 * e4 + 3] = t.w;
    }

    float o[DHz];
#pragma unroll
    for (int e = 0; e < DHz; e++) o[e] = 0.0f;
    float m = -1e30f, l = 0.0f;

    __shared__ float Ks[KT][DHz];
    __shared__ float Vs[KT][DHz];

    const int kend   = qt * 128 + 127;     // last key any thread in block needs
    const int ntiles = kend / KT + 1;

    for (int t = 0; t < ntiles; t++) {
        const int k0 = t * KT;
        __syncthreads();   // previous tile fully consumed
        // load K/V tile: 32 rows x 64 cols = 512 float4 each; 128 threads x 4
#pragma unroll
        for (int i = 0; i < 4; i++) {
            const int p   = threadIdx.x + i * 128;   // 0..511
            const int row = p >> 4;
            const int c4  = p & 15;
            const size_t kb = ((size_t)(b * Sz + k0 + row) * 3) * HD + HD + h * DHz + c4 * 4;
            *(float4*)&Ks[row][c4 * 4] = *(const float4*)(qkv + kb);
            *(float4*)&Vs[row][c4 * 4] = *(const float4*)(qkv + kb + HD);
        }
        __syncthreads();

        if (k0 <= qi) {
            float s[KT];
            float tmax = -1e30f;
            for (int j = 0; j < KT; j++) {
                float acc = 0.0f;
#pragma unroll
                for (int e4 = 0; e4 < DHz / 4; e4++) {
                    float4 kk = *(const float4*)&Ks[j][e4 * 4];
                    acc += q[4 * e4 + 0] * kk.x + q[4 * e4 + 1] * kk.y
                         + q[4 * e4 + 2] * kk.z + q[4 * e4 + 3] * kk.w;
                }
                acc *= 0.125f;                    // 1/sqrt(64)
                if (k0 + j > qi) acc = -1e30f;    // causal mask
                s[j] = acc;
                tmax = fmaxf(tmax, acc);
            }
            const float mnew = fmaxf(m, tmax);
            const float corr = __expf(m - mnew);
            l *= corr;
#pragma unroll
            for (int e = 0; e < DHz; e++) o[e] *= corr;
            for (int j = 0; j < KT; j++) {
                const float p = __expf(s[j] - mnew);
                l += p;
#pragma unroll
                for (int e4 = 0; e4 < DHz / 4; e4++) {
                    float4 vv = *(const float4*)&Vs[j][e4 * 4];
                    o[4 * e4 + 0] += p * vv.x;
                    o[4 * e4 + 1] += p * vv.y;
                    o[4 * e4 + 2] += p * vv.z;
                    o[4 * e4 + 3] += p * vv.w;
                }
            }
            m = mnew;
        }
    }

    const float inv = 1.0f / l;
    const size_t ob = (size_t)(b * Sz + qi) * HD + h * DHz;
#pragma unroll
    for (int e4 = 0; e4 < DHz / 4; e4++) {
        float4 t;
        t.x = o[4 * e4 + 0] * inv;
        t.y = o[4 * e4 + 1] * inv;
        t.z = o[4 * e4 + 2] * inv;
        t.w = o[4 * e4 + 3] * inv;
        *(float4*)(g_attn + ob + e4 * 4) = t;
    }
}

// ---------------------------------------------------------------------------
// Launch
// ---------------------------------------------------------------------------
extern "C" void kernel_launch(void* const* d_in, const int* in_sizes, int n_in,
                              void* d_out, int out_size)
{
    const float* x     = (const float*)d_in[0];   // [B,S,D]
    const float* w_qkv = (const float*)d_in[1];   // [D,3,H,DH]
    const float* b_qkv = (const float*)d_in[2];   // [3,H,DH]
    const float* w_out = (const float*)d_in[3];   // [H,DH,D]
    const float* b_out = (const float*)d_in[4];   // [D]
    float* out = (float*)d_out;                   // [B,S,D]

    float* qkv_ptr  = nullptr;
    float* attn_ptr = nullptr;
    cudaGetSymbolAddress((void**)&qkv_ptr,  g_qkv);
    cudaGetSymbolAddress((void**)&attn_ptr, g_attn);

    // 1) QKV projection: [8192,1024] @ [1024,3072] + bias
    {
        dim3 grid(QKV_N / 128, Mrows / 128);
        sgemm_bias<<<grid, 256>>>(Mrows, QKV_N, Dz, x, w_qkv, b_qkv, qkv_ptr);
    }
    // 2) causal attention
    {
        dim3 grid(Bz * Hz, Sz / 128);
        attn_kernel<<<grid, 128>>>();
    }
    // 3) output projection: [8192,1024] @ [1024,1024] + bias
    {
        dim3 grid(Dz / 128, Mrows / 128);
        sgemm_bias<<<grid, 256>>>(Mrows, Dz, HD, attn_ptr, w_out, b_out, out);
    }
}

// round 4
// speedup vs baseline: 1.0097x; 1.0097x over previous
#include <cuda_runtime.h>
#include <cstdint>

// Problem shape (fixed)
#define Bz 4
#define Sz 2048
#define Dz 1024
#define Hz 16
#define DHz 64
#define HD (Hz*DHz)          // 1024
#define QKV_N (3*HD)         // 3072
#define Mrows (Bz*Sz)        // 8192

// Scratch (device globals: allocation-free per harness rules)
__device__ float g_qkv[(size_t)Mrows * QKV_N];   // [b,s,t,h,e]  96 MB
__device__ float g_attn[(size_t)Mrows * HD];     // [b,s,h,e]    32 MB

// ---------------------------------------------------------------------------
// TF32x3 tensor-core GEMM + bias: C[M,N] = A[M,K] @ B[K,N] + bias[N]
// Error-compensated: a = ah + al (tf32 split), D += Ah*Bh + Ah*Bl + Al*Bh.
// Block 128x128, BK=16, 8 warps (64x32 warp tiles).
// SINGLE-stage static smem (37.9KB < 48KB: no cudaFuncSetAttribute needed),
// global->reg prefetch hides load latency across the compute phase.
// Requires M%128==0, N%128==0, K%16==0.
// ---------------------------------------------------------------------------
#define AST 20            // A smem row stride (floats): conflict-free frag loads
#define BST 136           // B smem row stride (floats): conflict-free frag loads
#define ASZ (128*AST)     // 2560 floats
#define BSZ (16*BST)      // 2176 floats
#define SMEM_FLOATS (2*ASZ + 2*BSZ)   // 9472 floats = 37888 bytes

__device__ __forceinline__ uint32_t f2tf32(float x) {
    uint32_t r;
    asm("cvt.rna.tf32.f32 %0, %1;" : "=r"(r) : "f"(x));
    return r;
}

__device__ __forceinline__ void mma_tf32(float c[4],
                                         uint32_t a0, uint32_t a1, uint32_t a2, uint32_t a3,
                                         uint32_t b0, uint32_t b1) {
    asm volatile(
        "mma.sync.aligned.m16n8k8.row.col.f32.tf32.tf32.f32 "
        "{%0,%1,%2,%3}, {%4,%5,%6,%7}, {%8,%9}, {%0,%1,%2,%3};"
        : "+f"(c[0]), "+f"(c[1]), "+f"(c[2]), "+f"(c[3])
        : "r"(a0), "r"(a1), "r"(a2), "r"(a3), "r"(b0), "r"(b1));
}

__global__ __launch_bounds__(256)
void gemm_tf32x3(int M, int N, int K,
                 const float* __restrict__ A,
                 const float* __restrict__ Bm,
                 const float* __restrict__ bias,
                 float* __restrict__ C)
{
    __shared__ float smem[SMEM_FLOATS];
    float* As_hi = smem;              // [ASZ]
    float* As_lo = smem + ASZ;
    float* Bs_hi = smem + 2*ASZ;      // [BSZ]
    float* Bs_lo = smem + 2*ASZ + BSZ;

    const int tid  = threadIdx.x;
    const int lane = tid & 31;
    const int warp = tid >> 5;
    const int wm   = warp >> 2;          // 0..1 : 64-row slab
    const int wn   = warp & 3;           // 0..3 : 32-col slab
    const int g    = lane >> 2;          // groupID 0..7
    const int t    = lane & 3;           // threadID_in_group

    A    += (size_t)blockIdx.y * 128 * K;
    Bm   += (size_t)blockIdx.x * 128;
    C    += (size_t)blockIdx.y * 128 * N + (size_t)blockIdx.x * 128;
    bias += (size_t)blockIdx.x * 128;

    // loader mapping
    const int arow = tid >> 2;           // 0..63  (chunk i adds 64)
    const int aq   = (tid & 3) * 4;      // col within BK
    const int brow = tid >> 5;           // 0..7   (chunk i adds 8)
    const int bc   = (tid & 31) * 4;     // col within BN

    float4 a4[2], b4[2];

    auto LDG = [&](int k0) {
#pragma unroll
        for (int i = 0; i < 2; i++) {
            a4[i] = *(const float4*)(A + (size_t)(arow + 64*i) * K + k0 + aq);
            b4[i] = *(const float4*)(Bm + (size_t)(k0 + brow + 8*i) * N + bc);
        }
    };
    auto STS = [&]() {
#pragma unroll
        for (int i = 0; i < 2; i++) {
            const float* av = (const float*)&a4[i];
            const float* bv = (const float*)&b4[i];
#pragma unroll
            for (int j = 0; j < 4; j++) {
                float va = av[j];
                uint32_t h = f2tf32(va);
                uint32_t l = f2tf32(va - __uint_as_float(h));
                As_hi[(arow + 64*i)*AST + aq + j] = __uint_as_float(h);
                As_lo[(arow + 64*i)*AST + aq + j] = __uint_as_float(l);
                float vb = bv[j];
                uint32_t hb = f2tf32(vb);
                uint32_t lb = f2tf32(vb - __uint_as_float(hb));
                Bs_hi[(brow + 8*i)*BST + bc + j] = __uint_as_float(hb);
                Bs_lo[(brow + 8*i)*BST + bc + j] = __uint_as_float(lb);
            }
        }
    };

    float acc[4][4][4];
#pragma unroll
    for (int i = 0; i < 4; i++)
#pragma unroll
        for (int j = 0; j < 4; j++)
#pragma unroll
            for (int r = 0; r < 4; r++) acc[i][j][r] = 0.0f;

    LDG(0);
    STS();
    __syncthreads();

    const int nk = K / 16;
    for (int kt = 0; kt < nk; kt++) {
        // prefetch next tile into registers while computing from smem
        if (kt + 1 < nk) LDG((kt + 1) * 16);

#pragma unroll
        for (int kk = 0; kk < 16; kk += 8) {
            uint32_t bh[4][2], bl[4][2];
#pragma unroll
            for (int nt = 0; nt < 4; nt++) {
                const int nb = wn*32 + nt*8 + g;
                bh[nt][0] = __float_as_uint(Bs_hi[(kk + t    )*BST + nb]);
                bh[nt][1] = __float_as_uint(Bs_hi[(kk + t + 4)*BST + nb]);
                bl[nt][0] = __float_as_uint(Bs_lo[(kk + t    )*BST + nb]);
                bl[nt][1] = __float_as_uint(Bs_lo[(kk + t + 4)*BST + nb]);
            }
#pragma unroll
            for (int mt = 0; mt < 4; mt++) {
                const int r0 = wm*64 + mt*16 + g;
                const int r1 = r0 + 8;
                uint32_t ah0 = __float_as_uint(As_hi[r0*AST + kk + t]);
                uint32_t ah1 = __float_as_uint(As_hi[r1*AST + kk + t]);
                uint32_t ah2 = __float_as_uint(As_hi[r0*AST + kk + t + 4]);
                uint32_t ah3 = __float_as_uint(As_hi[r1*AST + kk + t + 4]);
#pragma unroll
                for (int nt = 0; nt < 4; nt++)
                    mma_tf32(acc[mt][nt], ah0, ah1, ah2, ah3, bh[nt][0], bh[nt][1]);
#pragma unroll
                for (int nt = 0; nt < 4; nt++)
                    mma_tf32(acc[mt][nt], ah0, ah1, ah2, ah3, bl[nt][0], bl[nt][1]);
                uint32_t al0 = __float_as_uint(As_lo[r0*AST + kk + t]);
                uint32_t al1 = __float_as_uint(As_lo[r1*AST + kk + t]);
                uint32_t al2 = __float_as_uint(As_lo[r0*AST + kk + t + 4]);
                uint32_t al3 = __float_as_uint(As_lo[r1*AST + kk + t + 4]);
#pragma unroll
                for (int nt = 0; nt < 4; nt++)
                    mma_tf32(acc[mt][nt], al0, al1, al2, al3, bh[nt][0], bh[nt][1]);
            }
        }

        __syncthreads();   // everyone done reading smem
        if (kt + 1 < nk) {
            STS();         // write the prefetched tile
            __syncthreads();
        }
    }

    // epilogue: bias + store (float2 per C frag row)
#pragma unroll
    for (int mt = 0; mt < 4; mt++) {
#pragma unroll
        for (int nt = 0; nt < 4; nt++) {
            const int r = wm*64 + mt*16 + g;
            const int c = wn*32 + nt*8 + 2*t;
            const float b0v = bias[c];
            const float b1v = bias[c + 1];
            float2 v0 = make_float2(acc[mt][nt][0] + b0v, acc[mt][nt][1] + b1v);
            float2 v1 = make_float2(acc[mt][nt][2] + b0v, acc[mt][nt][3] + b1v);
            *(float2*)(C + (size_t)r * N + c)       = v0;
            *(float2*)(C + (size_t)(r + 8) * N + c) = v1;
        }
    }
}

// ---------------------------------------------------------------------------
// Causal flash attention (fp32). One thread = one query row. (unchanged)
// ---------------------------------------------------------------------------
__global__ __launch_bounds__(128)
void attn_kernel()
{
    constexpr int KT = 32;
    const int bh = blockIdx.x;
    const int b  = bh / Hz;
    const int h  = bh % Hz;
    const int qt = blockIdx.y;
    const int qi = qt * 128 + threadIdx.x;

    const float* __restrict__ qkv = g_qkv;
    const size_t qbase = ((size_t)(b * Sz + qi) * 3) * HD + h * DHz;

    float q[DHz];
#pragma unroll
    for (int e4 = 0; e4 < DHz / 4; e4++) {
        float4 t = *(const float4*)(qkv + qbase + e4 * 4);
        q[4 * e4 + 0] = t.x; q[4 * e4 + 1] = t.y;
        q[4 * e4 + 2] = t.z; q[4 * e4 + 3] = t.w;
    }

    float o[DHz];
#pragma unroll
    for (int e = 0; e < DHz; e++) o[e] = 0.0f;
    float m = -1e30f, l = 0.0f;

    __shared__ float Ks[KT][DHz];
    __shared__ float Vs[KT][DHz];

    const int kend   = qt * 128 + 127;
    const int ntiles = kend / KT + 1;

    for (int t = 0; t < ntiles; t++) {
        const int k0 = t * KT;
        __syncthreads();
#pragma unroll
        for (int i = 0; i < 4; i++) {
            const int p   = threadIdx.x + i * 128;
            const int row = p >> 4;
            const int c4  = p & 15;
            const size_t kb = ((size_t)(b * Sz + k0 + row) * 3) * HD + HD + h * DHz + c4 * 4;
            *(float4*)&Ks[row][c4 * 4] = *(const float4*)(qkv + kb);
            *(float4*)&Vs[row][c4 * 4] = *(const float4*)(qkv + kb + HD);
        }
        __syncthreads();

        if (k0 <= qi) {
            float s[KT];
            float tmax = -1e30f;
            for (int j = 0; j < KT; j++) {
                float acc = 0.0f;
#pragma unroll
                for (int e4 = 0; e4 < DHz / 4; e4++) {
                    float4 kk = *(const float4*)&Ks[j][e4 * 4];
                    acc += q[4 * e4 + 0] * kk.x + q[4 * e4 + 1] * kk.y
                         + q[4 * e4 + 2] * kk.z + q[4 * e4 + 3] * kk.w;
                }
                acc *= 0.125f;
                if (k0 + j > qi) acc = -1e30f;
                s[j] = acc;
                tmax = fmaxf(tmax, acc);
            }
            const float mnew = fmaxf(m, tmax);
            const float corr = __expf(m - mnew);
            l *= corr;
#pragma unroll
            for (int e = 0; e < DHz; e++) o[e] *= corr;
            for (int j = 0; j < KT; j++) {
                const float p = __expf(s[j] - mnew);
                l += p;
#pragma unroll
                for (int e4 = 0; e4 < DHz / 4; e4++) {
                    float4 vv = *(const float4*)&Vs[j][e4 * 4];
                    o[4 * e4 + 0] += p * vv.x;
                    o[4 * e4 + 1] += p * vv.y;
                    o[4 * e4 + 2] += p * vv.z;
                    o[4 * e4 + 3] += p * vv.w;
                }
            }
            m = mnew;
        }
    }

    const float inv = 1.0f / l;
    const size_t ob = (size_t)(b * Sz + qi) * HD + h * DHz;
#pragma unroll
    for (int e4 = 0; e4 < DHz / 4; e4++) {
        float4 t;
        t.x = o[4 * e4 + 0] * inv;
        t.y = o[4 * e4 + 1] * inv;
        t.z = o[4 * e4 + 2] * inv;
        t.w = o[4 * e4 + 3] * inv;
        *(float4*)(g_attn + ob + e4 * 4) = t;
    }
}

// ---------------------------------------------------------------------------
// Launch — plain kernel launches only (no attribute calls, no dynamic smem)
// ---------------------------------------------------------------------------
extern "C" void kernel_launch(void* const* d_in, const int* in_sizes, int n_in,
                              void* d_out, int out_size)
{
    const float* x     = (const float*)d_in[0];
    const float* w_qkv = (const float*)d_in[1];
    const float* b_qkv = (const float*)d_in[2];
    const float* w_out = (const float*)d_in[3];
    const float* b_out = (const float*)d_in[4];
    float* out = (float*)d_out;

    float* qkv_ptr  = nullptr;
    float* attn_ptr = nullptr;
    cudaGetSymbolAddress((void**)&qkv_ptr,  g_qkv);
    cudaGetSymbolAddress((void**)&attn_ptr, g_attn);

    // 1) QKV projection: [8192,1024] @ [1024,3072] + bias
    {
        dim3 grid(QKV_N / 128, Mrows / 128);
        gemm_tf32x3<<<grid, 256>>>(Mrows, QKV_N, Dz, x, w_qkv, b_qkv, qkv_ptr);
    }
    // 2) causal attention
    {
        dim3 grid(Bz * Hz, Sz / 128);
        attn_kernel<<<grid, 128>>>();
    }
    // 3) output projection: [8192,1024] @ [1024,1024] + bias
    {
        dim3 grid(Dz / 128, Mrows / 128);
        gemm_tf32x3<<<grid, 256>>>(Mrows, Dz, HD, attn_ptr, w_out, b_out, out);
    }
}

// round 5
// speedup vs baseline: 1.1788x; 1.1675x over previous
#include <cuda_runtime.h>
#include <cstdint>

// Problem shape (fixed)
#define Bz 4
#define Sz 2048
#define Dz 1024
#define Hz 16
#define DHz 64
#define HD (Hz*DHz)          // 1024
#define QKV_N (3*HD)         // 3072
#define Mrows (Bz*Sz)        // 8192

// Scratch (device globals: allocation-free per harness rules)
__device__ float g_qkv[(size_t)Mrows * QKV_N];   // [b,s,t,h,e]  96 MB
__device__ float g_attn[(size_t)Mrows * HD];     // [b,s,h,e]    32 MB

// ---------------------------------------------------------------------------
// TF32x3 tensor-core GEMM + bias: C[M,N] = A[M,K] @ B[K,N] + bias[N]
// Raw fp32 in smem (hi/lo tf32 split at fragment-load time), cp.async
// double-buffered, 2 CTAs/SM. Block 128x128, BK=16, 8 warps (64x32 tiles).
// Requires M%128==0, N%128==0, K%16==0.
// ---------------------------------------------------------------------------
#define AST 20            // A smem row stride (floats): 80B = 5x16B aligned
#define BST 136           // B smem row stride (floats): 544B = 34x16B aligned
#define ASZ (128*AST)     // 2560 floats per stage
#define BSZ (16*BST)      // 2176 floats per stage
// static smem: 2*(ASZ+BSZ)*4 = 37888 bytes

__device__ __forceinline__ uint32_t f2tf32(float x) {
    uint32_t r;
    asm("cvt.rna.tf32.f32 %0, %1;" : "=r"(r) : "f"(x));
    return r;
}

__device__ __forceinline__ void cp16(uint32_t dst, const float* src) {
    asm volatile("cp.async.ca.shared.global [%0], [%1], 16;"
                 :: "r"(dst), "l"(src) : "memory");
}

__device__ __forceinline__ void mma_tf32(float c[4],
                                         uint32_t a0, uint32_t a1, uint32_t a2, uint32_t a3,
                                         uint32_t b0, uint32_t b1) {
    asm volatile(
        "mma.sync.aligned.m16n8k8.row.col.f32.tf32.tf32.f32 "
        "{%0,%1,%2,%3}, {%4,%5,%6,%7}, {%8,%9}, {%0,%1,%2,%3};"
        : "+f"(c[0]), "+f"(c[1]), "+f"(c[2]), "+f"(c[3])
        : "r"(a0), "r"(a1), "r"(a2), "r"(a3), "r"(b0), "r"(b1));
}

__global__ __launch_bounds__(256, 2)
void gemm_tf32x3(int M, int N, int K,
                 const float* __restrict__ A,
                 const float* __restrict__ Bm,
                 const float* __restrict__ bias,
                 float* __restrict__ C)
{
    __shared__ float As[2][ASZ];
    __shared__ float Bs[2][BSZ];

    const int tid  = threadIdx.x;
    const int lane = tid & 31;
    const int warp = tid >> 5;
    const int wm   = warp >> 2;          // 0..1 : 64-row slab
    const int wn   = warp & 3;           // 0..3 : 32-col slab
    const int g    = lane >> 2;          // groupID 0..7
    const int t    = lane & 3;           // threadID_in_group

    A    += (size_t)blockIdx.y * 128 * K;
    Bm   += (size_t)blockIdx.x * 128;
    C    += (size_t)blockIdx.y * 128 * N + (size_t)blockIdx.x * 128;
    bias += (size_t)blockIdx.x * 128;

    // loader mapping: 256 threads, 2 x 16B each for A and B
    const int arow = tid >> 2;           // 0..63  (chunk i adds 64)
    const int aq   = (tid & 3) * 4;      // col within BK
    const int brow = tid >> 5;           // 0..7   (chunk i adds 8)
    const int bc   = (tid & 31) * 4;     // col within BN

    const uint32_t as_u = (uint32_t)__cvta_generic_to_shared(&As[0][0]);
    const uint32_t bs_u = (uint32_t)__cvta_generic_to_shared(&Bs[0][0]);

    auto load_stage = [&](int kt, int s) {
        const int k0 = kt * 16;
#pragma unroll
        for (int i = 0; i < 2; i++) {
            cp16(as_u + (uint32_t)(s*ASZ + (arow + 64*i)*AST + aq) * 4,
                 A + (size_t)(arow + 64*i) * K + k0 + aq);
            cp16(bs_u + (uint32_t)(s*BSZ + (brow + 8*i)*BST + bc) * 4,
                 Bm + (size_t)(k0 + brow + 8*i) * N + bc);
        }
        asm volatile("cp.async.commit_group;" ::: "memory");
    };

    float acc[4][4][4];
#pragma unroll
    for (int i = 0; i < 4; i++)
#pragma unroll
        for (int j = 0; j < 4; j++)
#pragma unroll
            for (int r = 0; r < 4; r++) acc[i][j][r] = 0.0f;

    load_stage(0, 0);

    const int nk = K / 16;
    for (int kt = 0; kt < nk; kt++) {
        const int s = kt & 1;
        if (kt + 1 < nk) {
            load_stage(kt + 1, s ^ 1);
            asm volatile("cp.async.wait_group 1;" ::: "memory");
        } else {
            asm volatile("cp.async.wait_group 0;" ::: "memory");
        }
        __syncthreads();   // stage s fully resident for all threads

        const float* __restrict__ Ab = As[s];
        const float* __restrict__ Bb = Bs[s];

#pragma unroll
        for (int kk = 0; kk < 16; kk += 8) {
            // B fragments: load raw f32, split into tf32 hi/lo
            uint32_t bh[4][2], bl[4][2];
#pragma unroll
            for (int nt = 0; nt < 4; nt++) {
                const int nb = wn*32 + nt*8 + g;
                const float v0 = Bb[(kk + t    )*BST + nb];
                const float v1 = Bb[(kk + t + 4)*BST + nb];
                bh[nt][0] = f2tf32(v0);
                bl[nt][0] = f2tf32(v0 - __uint_as_float(bh[nt][0]));
                bh[nt][1] = f2tf32(v1);
                bl[nt][1] = f2tf32(v1 - __uint_as_float(bh[nt][1]));
            }
#pragma unroll
            for (int mt = 0; mt < 4; mt++) {
                const int r0 = wm*64 + mt*16 + g;
                const int r1 = r0 + 8;
                const float a0 = Ab[r0*AST + kk + t];
                const float a1 = Ab[r1*AST + kk + t];
                const float a2 = Ab[r0*AST + kk + t + 4];
                const float a3 = Ab[r1*AST + kk + t + 4];
                const uint32_t ah0 = f2tf32(a0), ah1 = f2tf32(a1);
                const uint32_t ah2 = f2tf32(a2), ah3 = f2tf32(a3);
#pragma unroll
                for (int nt = 0; nt < 4; nt++)
                    mma_tf32(acc[mt][nt], ah0, ah1, ah2, ah3, bh[nt][0], bh[nt][1]);
#pragma unroll
                for (int nt = 0; nt < 4; nt++)
                    mma_tf32(acc[mt][nt], ah0, ah1, ah2, ah3, bl[nt][0], bl[nt][1]);
                const uint32_t al0 = f2tf32(a0 - __uint_as_float(ah0));
                const uint32_t al1 = f2tf32(a1 - __uint_as_float(ah1));
                const uint32_t al2 = f2tf32(a2 - __uint_as_float(ah2));
                const uint32_t al3 = f2tf32(a3 - __uint_as_float(ah3));
#pragma unroll
                for (int nt = 0; nt < 4; nt++)
                    mma_tf32(acc[mt][nt], al0, al1, al2, al3, bh[nt][0], bh[nt][1]);
            }
        }

        __syncthreads();   // all reads of stage s done before it is re-filled
    }

    // epilogue: bias + store (float2 per C frag row)
#pragma unroll
    for (int mt = 0; mt < 4; mt++) {
#pragma unroll
        for (int nt = 0; nt < 4; nt++) {
            const int r = wm*64 + mt*16 + g;
            const int c = wn*32 + nt*8 + 2*t;
            const float b0v = bias[c];
            const float b1v = bias[c + 1];
            float2 v0 = make_float2(acc[mt][nt][0] + b0v, acc[mt][nt][1] + b1v);
            float2 v1 = make_float2(acc[mt][nt][2] + b0v, acc[mt][nt][3] + b1v);
            *(float2*)(C + (size_t)r * N + c)       = v0;
            *(float2*)(C + (size_t)(r + 8) * N + c) = v1;
        }
    }
}

// ---------------------------------------------------------------------------
// Causal flash attention (fp32). One thread = one query row. (unchanged)
// ---------------------------------------------------------------------------
__global__ __launch_bounds__(128)
void attn_kernel()
{
    constexpr int KT = 32;
    const int bh = blockIdx.x;
    const int b  = bh / Hz;
    const int h  = bh % Hz;
    const int qt = blockIdx.y;
    const int qi = qt * 128 + threadIdx.x;

    const float* __restrict__ qkv = g_qkv;
    const size_t qbase = ((size_t)(b * Sz + qi) * 3) * HD + h * DHz;

    float q[DHz];
#pragma unroll
    for (int e4 = 0; e4 < DHz / 4; e4++) {
        float4 t = *(const float4*)(qkv + qbase + e4 * 4);
        q[4 * e4 + 0] = t.x; q[4 * e4 + 1] = t.y;
        q[4 * e4 + 2] = t.z; q[4 * e4 + 3] = t.w;
    }

    float o[DHz];
#pragma unroll
    for (int e = 0; e < DHz; e++) o[e] = 0.0f;
    float m = -1e30f, l = 0.0f;

    __shared__ float Ks[KT][DHz];
    __shared__ float Vs[KT][DHz];

    const int kend   = qt * 128 + 127;
    const int ntiles = kend / KT + 1;

    for (int t = 0; t < ntiles; t++) {
        const int k0 = t * KT;
        __syncthreads();
#pragma unroll
        for (int i = 0; i < 4; i++) {
            const int p   = threadIdx.x + i * 128;
            const int row = p >> 4;
            const int c4  = p & 15;
            const size_t kb = ((size_t)(b * Sz + k0 + row) * 3) * HD + HD + h * DHz + c4 * 4;
            *(float4*)&Ks[row][c4 * 4] = *(const float4*)(qkv + kb);
            *(float4*)&Vs[row][c4 * 4] = *(const float4*)(qkv + kb + HD);
        }
        __syncthreads();

        if (k0 <= qi) {
            float s[KT];
            float tmax = -1e30f;
            for (int j = 0; j < KT; j++) {
                float acc = 0.0f;
#pragma unroll
                for (int e4 = 0; e4 < DHz / 4; e4++) {
                    float4 kk = *(const float4*)&Ks[j][e4 * 4];
                    acc += q[4 * e4 + 0] * kk.x + q[4 * e4 + 1] * kk.y
                         + q[4 * e4 + 2] * kk.z + q[4 * e4 + 3] * kk.w;
                }
                acc *= 0.125f;
                if (k0 + j > qi) acc = -1e30f;
                s[j] = acc;
                tmax = fmaxf(tmax, acc);
            }
            const float mnew = fmaxf(m, tmax);
            const float corr = __expf(m - mnew);
            l *= corr;
#pragma unroll
            for (int e = 0; e < DHz; e++) o[e] *= corr;
            for (int j = 0; j < KT; j++) {
                const float p = __expf(s[j] - mnew);
                l += p;
#pragma unroll
                for (int e4 = 0; e4 < DHz / 4; e4++) {
                    float4 vv = *(const float4*)&Vs[j][e4 * 4];
                    o[4 * e4 + 0] += p * vv.x;
                    o[4 * e4 + 1] += p * vv.y;
                    o[4 * e4 + 2] += p * vv.z;
                    o[4 * e4 + 3] += p * vv.w;
                }
            }
            m = mnew;
        }
    }

    const float inv = 1.0f / l;
    const size_t ob = (size_t)(b * Sz + qi) * HD + h * DHz;
#pragma unroll
    for (int e4 = 0; e4 < DHz / 4; e4++) {
        float4 t;
        t.x = o[4 * e4 + 0] * inv;
        t.y = o[4 * e4 + 1] * inv;
        t.z = o[4 * e4 + 2] * inv;
        t.w = o[4 * e4 + 3] * inv;
        *(float4*)(g_attn + ob + e4 * 4) = t;
    }
}

// ---------------------------------------------------------------------------
// Launch — plain kernel launches only
// ---------------------------------------------------------------------------
extern "C" void kernel_launch(void* const* d_in, const int* in_sizes, int n_in,
                              void* d_out, int out_size)
{
    const float* x     = (const float*)d_in[0];
    const float* w_qkv = (const float*)d_in[1];
    const float* b_qkv = (const float*)d_in[2];
    const float* w_out = (const float*)d_in[3];
    const float* b_out = (const float*)d_in[4];
    float* out = (float*)d_out;

    float* qkv_ptr  = nullptr;
    float* attn_ptr = nullptr;
    cudaGetSymbolAddress((void**)&qkv_ptr,  g_qkv);
    cudaGetSymbolAddress((void**)&attn_ptr, g_attn);

    // 1) QKV projection: [8192,1024] @ [1024,3072] + bias
    {
        dim3 grid(QKV_N / 128, Mrows / 128);
        gemm_tf32x3<<<grid, 256>>>(Mrows, QKV_N, Dz, x, w_qkv, b_qkv, qkv_ptr);
    }
    // 2) causal attention
    {
        dim3 grid(Bz * Hz, Sz / 128);
        attn_kernel<<<grid, 128>>>();
    }
    // 3) output projection: [8192,1024] @ [1024,1024] + bias
    {
        dim3 grid(Dz / 128, Mrows / 128);
        gemm_tf32x3<<<grid, 256>>>(Mrows, Dz, HD, attn_ptr, w_out, b_out, out);
    }
}

// round 7
// speedup vs baseline: 1.9404x; 1.6461x over previous
#include <cuda_runtime.h>
#include <cuda_bf16.h>
#include <cstdint>

// Problem shape (fixed)
#define Bz 4
#define Sz 2048
#define Dz 1024
#define Hz 16
#define DHz 64
#define HD (Hz*DHz)          // 1024
#define QKV_N (3*HD)         // 3072
#define Mrows (Bz*Sz)        // 8192

// Scratch (device globals: allocation-free per harness rules)
__device__ float g_qkv[(size_t)Mrows * QKV_N];   // [b,s,t,h,e]  96 MB
__device__ float g_attn[(size_t)Mrows * HD];     // [b,s,h,e]    32 MB

// ---------------------------------------------------------------------------
// Common helpers
// ---------------------------------------------------------------------------
__device__ __forceinline__ uint32_t f2tf32(float x) {
    uint32_t r;
    asm("cvt.rna.tf32.f32 %0, %1;" : "=r"(r) : "f"(x));
    return r;
}

__device__ __forceinline__ void cp16(uint32_t dst, const float* src) {
    asm volatile("cp.async.ca.shared.global [%0], [%1], 16;"
                 :: "r"(dst), "l"(src) : "memory");
}

__device__ __forceinline__ void mma_tf32(float c[4],
                                         uint32_t a0, uint32_t a1, uint32_t a2, uint32_t a3,
                                         uint32_t b0, uint32_t b1) {
    asm volatile(
        "mma.sync.aligned.m16n8k8.row.col.f32.tf32.tf32.f32 "
        "{%0,%1,%2,%3}, {%4,%5,%6,%7}, {%8,%9}, {%0,%1,%2,%3};"
        : "+f"(c[0]), "+f"(c[1]), "+f"(c[2]), "+f"(c[3])
        : "r"(a0), "r"(a1), "r"(a2), "r"(a3), "r"(b0), "r"(b1));
}

__device__ __forceinline__ void mma_bf16(float c[4],
                                         uint32_t a0, uint32_t a1, uint32_t a2, uint32_t a3,
                                         uint32_t b0, uint32_t b1) {
    asm volatile(
        "mma.sync.aligned.m16n8k16.row.col.f32.bf16.bf16.f32 "
        "{%0,%1,%2,%3}, {%4,%5,%6,%7}, {%8,%9}, {%0,%1,%2,%3};"
        : "+f"(c[0]), "+f"(c[1]), "+f"(c[2]), "+f"(c[3])
        : "r"(a0), "r"(a1), "r"(a2), "r"(a3), "r"(b0), "r"(b1));
}

// split (x,y) into packed bf16x2 hi and residual lo.  low half = x (lower k).
__device__ __forceinline__ void split2(float x, float y, uint32_t& hi, uint32_t& lo) {
    __nv_bfloat162 h = __floats2bfloat162_rn(x, y);
    float2 hf = __bfloat1622float2(h);
    __nv_bfloat162 l = __floats2bfloat162_rn(x - hf.x, y - hf.y);
    hi = *reinterpret_cast<uint32_t*>(&h);
    lo = *reinterpret_cast<uint32_t*>(&l);
}

// ---------------------------------------------------------------------------
// TF32x3 tensor-core GEMM + bias (unchanged from R5, smem 16B-aligned)
// ---------------------------------------------------------------------------
#define AST 20
#define BST 136
#define ASZ (128*AST)
#define BSZ (16*BST)

__global__ __launch_bounds__(256, 2)
void gemm_tf32x3(int M, int N, int K,
                 const float* __restrict__ A,
                 const float* __restrict__ Bm,
                 const float* __restrict__ bias,
                 float* __restrict__ C)
{
    __shared__ __align__(16) float As[2][ASZ];
    __shared__ __align__(16) float Bs[2][BSZ];

    const int tid  = threadIdx.x;
    const int lane = tid & 31;
    const int warp = tid >> 5;
    const int wm   = warp >> 2;
    const int wn   = warp & 3;
    const int g    = lane >> 2;
    const int t    = lane & 3;

    A    += (size_t)blockIdx.y * 128 * K;
    Bm   += (size_t)blockIdx.x * 128;
    C    += (size_t)blockIdx.y * 128 * N + (size_t)blockIdx.x * 128;
    bias += (size_t)blockIdx.x * 128;

    const int arow = tid >> 2;
    const int aq   = (tid & 3) * 4;
    const int brow = tid >> 5;
    const int bc   = (tid & 31) * 4;

    const uint32_t as_u = (uint32_t)__cvta_generic_to_shared(&As[0][0]);
    const uint32_t bs_u = (uint32_t)__cvta_generic_to_shared(&Bs[0][0]);

    auto load_stage = [&](int kt, int s) {
        const int k0 = kt * 16;
#pragma unroll
        for (int i = 0; i < 2; i++) {
            cp16(as_u + (uint32_t)(s*ASZ + (arow + 64*i)*AST + aq) * 4,
                 A + (size_t)(arow + 64*i) * K + k0 + aq);
            cp16(bs_u + (uint32_t)(s*BSZ + (brow + 8*i)*BST + bc) * 4,
                 Bm + (size_t)(k0 + brow + 8*i) * N + bc);
        }
        asm volatile("cp.async.commit_group;" ::: "memory");
    };

    float acc[4][4][4];
#pragma unroll
    for (int i = 0; i < 4; i++)
#pragma unroll
        for (int j = 0; j < 4; j++)
#pragma unroll
            for (int r = 0; r < 4; r++) acc[i][j][r] = 0.0f;

    load_stage(0, 0);

    const int nk = K / 16;
    for (int kt = 0; kt < nk; kt++) {
        const int s = kt & 1;
        if (kt + 1 < nk) {
            load_stage(kt + 1, s ^ 1);
            asm volatile("cp.async.wait_group 1;" ::: "memory");
        } else {
            asm volatile("cp.async.wait_group 0;" ::: "memory");
        }
        __syncthreads();

        const float* __restrict__ Ab = As[s];
        const float* __restrict__ Bb = Bs[s];

#pragma unroll
        for (int kk = 0; kk < 16; kk += 8) {
            uint32_t bh[4][2], bl[4][2];
#pragma unroll
            for (int nt = 0; nt < 4; nt++) {
                const int nb = wn*32 + nt*8 + g;
                const float v0 = Bb[(kk + t    )*BST + nb];
                const float v1 = Bb[(kk + t + 4)*BST + nb];
                bh[nt][0] = f2tf32(v0);
                bl[nt][0] = f2tf32(v0 - __uint_as_float(bh[nt][0]));
                bh[nt][1] = f2tf32(v1);
                bl[nt][1] = f2tf32(v1 - __uint_as_float(bh[nt][1]));
            }
#pragma unroll
            for (int mt = 0; mt < 4; mt++) {
                const int r0 = wm*64 + mt*16 + g;
                const int r1 = r0 + 8;
                const float a0 = Ab[r0*AST + kk + t];
                const float a1 = Ab[r1*AST + kk + t];
                const float a2 = Ab[r0*AST + kk + t + 4];
                const float a3 = Ab[r1*AST + kk + t + 4];
                const uint32_t ah0 = f2tf32(a0), ah1 = f2tf32(a1);
                const uint32_t ah2 = f2tf32(a2), ah3 = f2tf32(a3);
#pragma unroll
                for (int nt = 0; nt < 4; nt++)
                    mma_tf32(acc[mt][nt], ah0, ah1, ah2, ah3, bh[nt][0], bh[nt][1]);
#pragma unroll
                for (int nt = 0; nt < 4; nt++)
                    mma_tf32(acc[mt][nt], ah0, ah1, ah2, ah3, bl[nt][0], bl[nt][1]);
                const uint32_t al0 = f2tf32(a0 - __uint_as_float(ah0));
                const uint32_t al1 = f2tf32(a1 - __uint_as_float(ah1));
                const uint32_t al2 = f2tf32(a2 - __uint_as_float(ah2));
                const uint32_t al3 = f2tf32(a3 - __uint_as_float(ah3));
#pragma unroll
                for (int nt = 0; nt < 4; nt++)
                    mma_tf32(acc[mt][nt], al0, al1, al2, al3, bh[nt][0], bh[nt][1]);
            }
        }

        __syncthreads();
    }

#pragma unroll
    for (int mt = 0; mt < 4; mt++) {
#pragma unroll
        for (int nt = 0; nt < 4; nt++) {
            const int r = wm*64 + mt*16 + g;
            const int c = wn*32 + nt*8 + 2*t;
            const float b0v = bias[c];
            const float b1v = bias[c + 1];
            float2 v0 = make_float2(acc[mt][nt][0] + b0v, acc[mt][nt][1] + b1v);
            float2 v1 = make_float2(acc[mt][nt][2] + b0v, acc[mt][nt][3] + b1v);
            *(float2*)(C + (size_t)r * N + c)       = v0;
            *(float2*)(C + (size_t)(r + 8) * N + c) = v1;
        }
    }
}

// ---------------------------------------------------------------------------
// Tensor-core causal flash attention, bf16x3 error-compensated.
// CTA: 128 threads = 4 warps, 64 query rows (warp = 16-row slab).
// Key tiles of 32, cp.async double-buffered K/V in smem (f32, padded rows).
// ---------------------------------------------------------------------------
#define KT 32          // keys per tile
#define VPAD 68        // padded row stride (floats); 68*4=272B = 17x16B

__global__ __launch_bounds__(128)
void attn_tc()
{
    __shared__ __align__(16) float Ks[2][KT][VPAD];
    __shared__ __align__(16) float Vs[2][KT][VPAD];

    const int tid  = threadIdx.x;
    const int lane = tid & 31;
    const int warp = tid >> 5;          // 0..3
    const int g    = lane >> 2;         // 0..7
    const int t    = lane & 3;          // 0..3

    const int bh = blockIdx.x;
    const int b  = bh / Hz;
    const int h  = bh % Hz;
    const int q0 = blockIdx.y * 64;

    const float* __restrict__ qkv = g_qkv;

    // ---- stage Q (64 x 64) into smem (aliased over Ks), build A-fragments ----
    float* Qs = &Ks[0][0][0];           // 64*68 = 4352 floats = sizeof(Ks)
    {
#pragma unroll
        for (int i = 0; i < 8; i++) {
            const int p   = tid + i * 128;       // 0..1023
            const int row = p >> 4;
            const int c4  = p & 15;
            const size_t src = ((size_t)(b * Sz + q0 + row) * 3) * HD + h * DHz + c4 * 4;
            *(float4*)&Qs[row * VPAD + c4 * 4] = *(const float4*)(qkv + src);
        }
    }
    __syncthreads();

    uint32_t qh[4][4], ql[4][4];        // [dh k16 chunk][frag reg]
    {
        const int r0 = warp * 16 + g;
#pragma unroll
        for (int c = 0; c < 4; c++) {
            float2 q00 = *(const float2*)&Qs[ r0      * VPAD + 16*c + 2*t    ];
            float2 q10 = *(const float2*)&Qs[(r0 + 8) * VPAD + 16*c + 2*t    ];
            float2 q01 = *(const float2*)&Qs[ r0      * VPAD + 16*c + 2*t + 8];
            float2 q11 = *(const float2*)&Qs[(r0 + 8) * VPAD + 16*c + 2*t + 8];
            split2(q00.x, q00.y, qh[c][0], ql[c][0]);
            split2(q10.x, q10.y, qh[c][1], ql[c][1]);
            split2(q01.x, q01.y, qh[c][2], ql[c][2]);
            split2(q11.x, q11.y, qh[c][3], ql[c][3]);
        }
    }
    __syncthreads();   // done with Qs alias before K loads land

    float o[8][4];
#pragma unroll
    for (int j = 0; j < 8; j++)
#pragma unroll
        for (int r = 0; r < 4; r++) o[j][r] = 0.0f;
    float m0 = -1e30f, m1 = -1e30f, l0 = 0.0f, l1 = 0.0f;

    const uint32_t ks_u = (uint32_t)__cvta_generic_to_shared(&Ks[0][0][0]);
    const uint32_t vs_u = (uint32_t)__cvta_generic_to_shared(&Vs[0][0][0]);
    const int stageF = KT * VPAD;       // floats per stage

    auto load_tile = [&](int kt, int s) {
        const int k0 = kt * KT;
#pragma unroll
        for (int i = 0; i < 4; i++) {
            const int p   = tid + i * 128;       // 0..511
            const int row = p >> 4;
            const int c4  = p & 15;
            const size_t base = ((size_t)(b * Sz + k0 + row) * 3 + 1) * HD + h * DHz + c4 * 4;
            const uint32_t doff = (uint32_t)(s * stageF + row * VPAD + c4 * 4) * 4;
            cp16(ks_u + doff, qkv + base);        // K (t=1)
            cp16(vs_u + doff, qkv + base + HD);   // V (t=2)
        }
        asm volatile("cp.async.commit_group;" ::: "memory");
    };

    const int ntiles = q0 / KT + 2;
    const int r0row  = q0 + warp * 16 + g;
    const int r1row  = r0row + 8;

    load_tile(0, 0);

    for (int kt = 0; kt < ntiles; kt++) {
        const int s  = kt & 1;
        const int k0 = kt * KT;
        if (kt + 1 < ntiles) {
            load_tile(kt + 1, s ^ 1);
            asm volatile("cp.async.wait_group 1;" ::: "memory");
        } else {
            asm volatile("cp.async.wait_group 0;" ::: "memory");
        }
        __syncthreads();

        const float (*Kb)[VPAD] = Ks[s];
        const float (*Vb)[VPAD] = Vs[s];

        // ---- S = Q K^T (scaled), bf16x3 ----
        float sa[4][4];
#pragma unroll
        for (int j = 0; j < 4; j++)
#pragma unroll
            for (int r = 0; r < 4; r++) sa[j][r] = 0.0f;

#pragma unroll
        for (int c = 0; c < 4; c++) {
#pragma unroll
            for (int j = 0; j < 4; j++) {
                const float2 kv0 = *(const float2*)&Kb[8*j + g][16*c + 2*t    ];
                const float2 kv1 = *(const float2*)&Kb[8*j + g][16*c + 2*t + 8];
                uint32_t kh0, kl0, kh1, kl1;
                split2(kv0.x, kv0.y, kh0, kl0);
                split2(kv1.x, kv1.y, kh1, kl1);
                mma_bf16(sa[j], qh[c][0], qh[c][1], qh[c][2], qh[c][3], kh0, kh1);
                mma_bf16(sa[j], ql[c][0], ql[c][1], ql[c][2], ql[c][3], kh0, kh1);
                mma_bf16(sa[j], qh[c][0], qh[c][1], qh[c][2], qh[c][3], kl0, kl1);
            }
        }

        // scale + causal mask
        const bool need_mask = (k0 + KT - 1 > q0);
#pragma unroll
        for (int j = 0; j < 4; j++) {
#pragma unroll
            for (int r = 0; r < 4; r++) sa[j][r] *= 0.125f;
            if (need_mask) {
                const int col0 = k0 + 8*j + 2*t;
                const int col1 = col0 + 1;
                if (col0 > r0row) sa[j][0] = -1e30f;
                if (col1 > r0row) sa[j][1] = -1e30f;
                if (col0 > r1row) sa[j][2] = -1e30f;
                if (col1 > r1row) sa[j][3] = -1e30f;
            }
        }

        // ---- online softmax ----
        float tmax0 = -1e30f, tmax1 = -1e30f;
#pragma unroll
        for (int j = 0; j < 4; j++) {
            tmax0 = fmaxf(tmax0, fmaxf(sa[j][0], sa[j][1]));
            tmax1 = fmaxf(tmax1, fmaxf(sa[j][2], sa[j][3]));
        }
        tmax0 = fmaxf(tmax0, __shfl_xor_sync(0xffffffffu, tmax0, 1));
        tmax0 = fmaxf(tmax0, __shfl_xor_sync(0xffffffffu, tmax0, 2));
        tmax1 = fmaxf(tmax1, __shfl_xor_sync(0xffffffffu, tmax1, 1));
        tmax1 = fmaxf(tmax1, __shfl_xor_sync(0xffffffffu, tmax1, 2));

        const float mn0 = fmaxf(m0, tmax0);
        const float mn1 = fmaxf(m1, tmax1);
        const float corr0 = __expf(m0 - mn0);
        const float corr1 = __expf(m1 - mn1);
        m0 = mn0; m1 = mn1;

#pragma unroll
        for (int j = 0; j < 8; j++) {
            o[j][0] *= corr0; o[j][1] *= corr0;
            o[j][2] *= corr1; o[j][3] *= corr1;
        }

        float sum0 = 0.0f, sum1 = 0.0f;
#pragma unroll
        for (int j = 0; j < 4; j++) {
            sa[j][0] = __expf(sa[j][0] - m0);
            sa[j][1] = __expf(sa[j][1] - m0);
            sa[j][2] = __expf(sa[j][2] - m1);
            sa[j][3] = __expf(sa[j][3] - m1);
            sum0 += sa[j][0] + sa[j][1];
            sum1 += sa[j][2] + sa[j][3];
        }
        sum0 += __shfl_xor_sync(0xffffffffu, sum0, 1);
        sum0 += __shfl_xor_sync(0xffffffffu, sum0, 2);
        sum1 += __shfl_xor_sync(0xffffffffu, sum1, 1);
        sum1 += __shfl_xor_sync(0xffffffffu, sum1, 2);
        l0 = l0 * corr0 + sum0;
        l1 = l1 * corr1 + sum1;

        // ---- O += P V, bf16x3; P re-layout from accumulators is free ----
#pragma unroll
        for (int c2 = 0; c2 < 2; c2++) {
            uint32_t ah0, al0, ah1, al1, ah2, al2, ah3, al3;
            split2(sa[2*c2    ][0], sa[2*c2    ][1], ah0, al0);
            split2(sa[2*c2    ][2], sa[2*c2    ][3], ah1, al1);
            split2(sa[2*c2 + 1][0], sa[2*c2 + 1][1], ah2, al2);
            split2(sa[2*c2 + 1][2], sa[2*c2 + 1][3], ah3, al3);
#pragma unroll
            for (int j = 0; j < 8; j++) {
                const float v00 = Vb[16*c2 + 2*t    ][8*j + g];
                const float v01 = Vb[16*c2 + 2*t + 1][8*j + g];
                const float v10 = Vb[16*c2 + 2*t + 8][8*j + g];
                const float v11 = Vb[16*c2 + 2*t + 9][8*j + g];
                uint32_t vh0, vl0, vh1, vl1;
                split2(v00, v01, vh0, vl0);
                split2(v10, v11, vh1, vl1);
                mma_bf16(o[j], ah0, ah1, ah2, ah3, vh0, vh1);
                mma_bf16(o[j], al0, al1, al2, al3, vh0, vh1);
                mma_bf16(o[j], ah0, ah1, ah2, ah3, vl0, vl1);
            }
        }

        __syncthreads();   // stage consumed before refill
    }

    // ---- normalize + store ----
    const float inv0 = 1.0f / l0;
    const float inv1 = 1.0f / l1;
    const size_t ob0 = (size_t)(b * Sz + r0row) * HD + h * DHz;
    const size_t ob1 = (size_t)(b * Sz + r1row) * HD + h * DHz;
#pragma unroll
    for (int j = 0; j < 8; j++) {
        const int c = 8*j + 2*t;
        *(float2*)(g_attn + ob0 + c) = make_float2(o[j][0] * inv0, o[j][1] * inv0);
        *(float2*)(g_attn + ob1 + c) = make_float2(o[j][2] * inv1, o[j][3] * inv1);
    }
}

// ---------------------------------------------------------------------------
// Launch — plain kernel launches only
// ---------------------------------------------------------------------------
extern "C" void kernel_launch(void* const* d_in, const int* in_sizes, int n_in,
                              void* d_out, int out_size)
{
    const float* x     = (const float*)d_in[0];
    const float* w_qkv = (const float*)d_in[1];
    const float* b_qkv = (const float*)d_in[2];
    const float* w_out = (const float*)d_in[3];
    const float* b_out = (const float*)d_in[4];
    float* out = (float*)d_out;

    float* qkv_ptr  = nullptr;
    float* attn_ptr = nullptr;
    cudaGetSymbolAddress((void**)&qkv_ptr,  g_qkv);
    cudaGetSymbolAddress((void**)&attn_ptr, g_attn);

    // 1) QKV projection: [8192,1024] @ [1024,3072] + bias
    {
        dim3 grid(QKV_N / 128, Mrows / 128);
        gemm_tf32x3<<<grid, 256>>>(Mrows, QKV_N, Dz, x, w_qkv, b_qkv, qkv_ptr);
    }
    // 2) causal attention (tensor core)
    {
        dim3 grid(Bz * Hz, Sz / 64);
        attn_tc<<<grid, 128>>>();
    }
    // 3) output projection: [8192,1024] @ [1024,1024] + bias
    {
        dim3 grid(Dz / 128, Mrows / 128);
        gemm_tf32x3<<<grid, 256>>>(Mrows, Dz, HD, attn_ptr, w_out, b_out, out);
    }
}